// round 14
// baseline (speedup 1.0000x reference)
#include <cuda_runtime.h>
#include <cuda_bf16.h>
#include <math.h>
#include <stdint.h>

#define Bc 4
#define Sc 2048
#define Dc 512
#define Nc 16
#define DTR 32
#define BS (Bc*Sc)
#define BSD (BS*Dc)
#define CL 32
#define NCH (Sc/CL)
#define NSCAN (Bc*NCH*Dc*Nc)
#define NF 640                 // fused bwd GEMM width (512 bwd + 64 dbc + 64 pad)

// ---- fp32 scratch ----
__device__ float g_z1[BSD];
__device__ float g_bwd[BSD];
__device__ float g_dbc[BS*64];
__device__ float g_p[BSD];
__device__ float g_du[BSD];
__device__ float g_afin[NSCAN];   // also reused as wgemm fp32 scratch
__device__ float g_hfin[NSCAN];
__device__ float g_h0[NSCAN];
__device__ float g_biasf[NF];

// ---- split-bf16 operand buffers ----
__device__ __nv_bfloat16 g_xnh[BSD],  g_xnl[BSD];
__device__ __nv_bfloat16 g_z1h[BSD],  g_z1l[BSD];
__device__ __nv_bfloat16 g_dbch[BS*64], g_dbcl[BS*64];
__device__ __nv_bfloat16 g_wph[Dc*Dc], g_wpl[Dc*Dc];
__device__ __nv_bfloat16 g_wfuseh[NF*Dc], g_wfusel[NF*Dc];  // rows 576+ stay zero
__device__ __nv_bfloat16 g_wbrm[Dc*Dc], g_wbrml[Dc*Dc];     // W_bwd row-major split
__device__ __nv_bfloat16 g_wdbch[64*Dc], g_wdbcl[64*Dc];
__device__ __nv_bfloat16 g_wdth[Dc*DTR], g_wdtl[Dc*DTR];

// =====================================================================
// helpers
// =====================================================================
__device__ __forceinline__ void split1(float v, __nv_bfloat16& h, __nv_bfloat16& l)
{
    h = __float2bfloat16(v);
    l = __float2bfloat16(v - __bfloat162float(h));
}

__device__ __forceinline__ void mma16816(float* c, const uint32_t* a, const uint32_t* b)
{
    asm volatile(
        "mma.sync.aligned.m16n8k16.row.col.f32.bf16.bf16.f32 "
        "{%0,%1,%2,%3}, {%4,%5,%6,%7}, {%8,%9}, {%0,%1,%2,%3};\n"
        : "+f"(c[0]), "+f"(c[1]), "+f"(c[2]), "+f"(c[3])
        : "r"(a[0]), "r"(a[1]), "r"(a[2]), "r"(a[3]),
          "r"(b[0]), "r"(b[1]));
}

__device__ __forceinline__ void ldsm_x4(uint32_t* r, uint32_t addr)
{
    asm volatile("ldmatrix.sync.aligned.m8n8.x4.shared.b16 {%0,%1,%2,%3}, [%4];\n"
                 : "=r"(r[0]), "=r"(r[1]), "=r"(r[2]), "=r"(r[3]) : "r"(addr));
}

__device__ __forceinline__ void ldsm_x2(uint32_t* r, uint32_t addr)
{
    asm volatile("ldmatrix.sync.aligned.m8n8.x2.shared.b16 {%0,%1}, [%2];\n"
                 : "=r"(r[0]), "=r"(r[1]) : "r"(addr));
}

__device__ __forceinline__ void cp16(uint32_t dst_smem, const void* src_gmem)
{
    asm volatile("cp.async.ca.shared.global [%0], [%1], 16;\n"
                 :: "r"(dst_smem), "l"(src_gmem) : "memory");
}
#define CP_COMMIT() asm volatile("cp.async.commit_group;\n" ::: "memory")
#define CP_WAIT0()  asm volatile("cp.async.wait_group 0;\n" ::: "memory")

__device__ __forceinline__ int swz(int row, int kc)
{
    return row * 4 + (kc ^ ((row >> 1) & 3));
}

__device__ __forceinline__ void pow16n(float pv, float* dA)
{
    float p1 = pv, p2 = p1*p1, p4 = p2*p2, p8 = p4*p4;
    dA[0]=p1;        dA[1]=p2;        dA[2]=p2*p1;     dA[3]=p4;
    dA[4]=p4*p1;     dA[5]=p4*p2;     dA[6]=p4*dA[2];  dA[7]=p8;
    dA[8]=p8*p1;     dA[9]=p8*p2;     dA[10]=p8*dA[2]; dA[11]=p8*p4;
    dA[12]=p8*dA[4]; dA[13]=p8*dA[5]; dA[14]=p8*dA[6]; dA[15]=p8*p8;
}

// =====================================================================
// weight converts
// =====================================================================
// transpose + split: W[K][N] -> out[N][K]
__global__ void convert_w(const float* __restrict__ W, int K, int N,
                          __nv_bfloat16* __restrict__ oh,
                          __nv_bfloat16* __restrict__ ol)
{
    int idx = blockIdx.x * blockDim.x + threadIdx.x;
    if (idx >= K * N) return;
    int k = idx / N, n = idx % N;
    __nv_bfloat16 h, l;
    split1(W[idx], h, l);
    oh[n * K + k] = h;
    ol[n * K + k] = l;
}

// row-major split (no transpose)
__global__ void convert_rm(const float* __restrict__ W, int total,
                           __nv_bfloat16* __restrict__ oh,
                           __nv_bfloat16* __restrict__ ol)
{
    int idx = blockIdx.x * blockDim.x + threadIdx.x;
    if (idx >= total) return;
    __nv_bfloat16 h, l;
    split1(W[idx], h, l);
    oh[idx] = h;
    ol[idx] = l;
}

// fused bias vector: [0,512)=b_bwd, [512,576)=b_bwd @ W_dbc, rest 0
__global__ void biasf_kernel(const float* __restrict__ b_bwd,
                             const float* __restrict__ W_dbc,
                             float* __restrict__ biasf)
{
    int n = blockIdx.x * blockDim.x + threadIdx.x;
    if (n >= NF) return;
    if (n < 512) { biasf[n] = b_bwd[n]; return; }
    if (n < 576) {
        int c = n - 512;
        float s = 0.f;
        for (int j = 0; j < 512; j++)
            s = fmaf(b_bwd[j], W_dbc[j * 64 + c], s);
        biasf[n] = s;
        return;
    }
    biasf[n] = 0.f;
}

// =====================================================================
// LayerNorm -> split bf16
// =====================================================================
__global__ void ln_kernel(const float* __restrict__ x,
                          const float* __restrict__ gamma,
                          const float* __restrict__ beta,
                          __nv_bfloat16* __restrict__ xnh,
                          __nv_bfloat16* __restrict__ xnl)
{
    int row = blockIdx.x;
    int tid = threadIdx.x;
    const float4* xr = reinterpret_cast<const float4*>(x + (size_t)row * Dc);
    float4 v = xr[tid];
    float s = v.x + v.y + v.z + v.w;
    float q = v.x*v.x + v.y*v.y + v.z*v.z + v.w*v.w;
    #pragma unroll
    for (int o = 16; o; o >>= 1) {
        s += __shfl_xor_sync(0xffffffffu, s, o);
        q += __shfl_xor_sync(0xffffffffu, q, o);
    }
    __shared__ float ss[4], sq[4];
    if ((tid & 31) == 0) { ss[tid >> 5] = s; sq[tid >> 5] = q; }
    __syncthreads();
    s = ss[0] + ss[1] + ss[2] + ss[3];
    q = sq[0] + sq[1] + sq[2] + sq[3];
    float mean = s * (1.0f / Dc);
    float var  = q * (1.0f / Dc) - mean * mean;
    float rstd = rsqrtf(var + 1e-5f);
    float4 g  = reinterpret_cast<const float4*>(gamma)[tid];
    float4 bt = reinterpret_cast<const float4*>(beta)[tid];
    float ov[4];
    ov[0] = (v.x - mean) * rstd * g.x + bt.x;
    ov[1] = (v.y - mean) * rstd * g.y + bt.y;
    ov[2] = (v.z - mean) * rstd * g.z + bt.z;
    ov[3] = (v.w - mean) * rstd * g.w + bt.w;
    size_t base = (size_t)row * Dc + tid * 4;
    #pragma unroll
    for (int j = 0; j < 4; j++) {
        __nv_bfloat16 h, l;
        split1(ov[j], h, l);
        xnh[base + j] = h;
        xnl[base + j] = l;
    }
}

// =====================================================================
// v8/v9: BM=128 x BN=128 GEMM, 4 warps (64x64 warp tile), dyn smem
// EPI 0: C0 = v (+ split to C0h/C0l if given)
// EPI 1: p = 1/(1+e^v); delta = softplus; C0=p, C1=delta*aux
// EPI 3: fused bwd: n<512 -> C0 (bwd fp32, ld 512);
//        512<=n<576 -> C1 (dbc fp32, ld 64) + split to C0h/C0l; else skip
// =====================================================================
template<int EPI>
__global__ __launch_bounds__(128, 2)
void mma_gemm8(const __nv_bfloat16* __restrict__ Ah,
               const __nv_bfloat16* __restrict__ Al, int lda,
               const __nv_bfloat16* __restrict__ Bh,
               const __nv_bfloat16* __restrict__ Bl, int ldb,
               const float* __restrict__ bias,
               float* __restrict__ C0, float* __restrict__ C1,
               const float* __restrict__ aux,
               __nv_bfloat16* __restrict__ C0h,
               __nv_bfloat16* __restrict__ C0l,
               int M, int N, int K)
{
    constexpr int BM = 128, BN = 128;
    extern __shared__ __align__(16) uint4 dsm[];
    uint4* sAh = dsm;
    uint4* sAl = dsm + 2 * BM * 4;
    uint4* sBh = dsm + 4 * BM * 4;
    uint4* sBl = dsm + 4 * BM * 4 + 2 * BN * 4;

    uint32_t aAh = (uint32_t)__cvta_generic_to_shared(sAh);
    uint32_t aAl = (uint32_t)__cvta_generic_to_shared(sAl);
    uint32_t aBh = (uint32_t)__cvta_generic_to_shared(sBh);
    uint32_t aBl = (uint32_t)__cvta_generic_to_shared(sBl);

    int tid = threadIdx.x;
    int bm = blockIdx.y * BM;
    int bn = blockIdx.x * BN;
    int wid = tid >> 5, l = tid & 31;
    int wn = wid & 1, wm = wid >> 1;
    int m_off = wm * 64;
    int n_off = wn * 64;

    float acc[4][8][4];
    #pragma unroll
    for (int i = 0; i < 4; i++)
        #pragma unroll
        for (int j = 0; j < 8; j++)
            #pragma unroll
            for (int c = 0; c < 4; c++) acc[i][j][c] = 0.f;

    auto issue_tile = [&](int k0, int buf) {
        #pragma unroll
        for (int r = 0; r < 4; r++) {
            int v = tid + r * 128;
            int m = v >> 2, kc = v & 3;
            uint32_t dst = (uint32_t)((buf * BM * 4 + swz(m, kc)) * 16);
            cp16(aAh + dst, Ah + (size_t)(bm + m) * lda + k0 + kc * 8);
            cp16(aAl + dst, Al + (size_t)(bm + m) * lda + k0 + kc * 8);
        }
        #pragma unroll
        for (int r = 0; r < 4; r++) {
            int v = tid + r * 128;
            int n = v >> 2, kc = v & 3;
            uint32_t dst = (uint32_t)((buf * BN * 4 + swz(n, kc)) * 16);
            cp16(aBh + dst, Bh + (size_t)(bn + n) * ldb + k0 + kc * 8);
            cp16(aBl + dst, Bl + (size_t)(bn + n) * ldb + k0 + kc * 8);
        }
        CP_COMMIT();
    };

    issue_tile(0, 0);

    int buf = 0;
    for (int k0 = 0; k0 < K; k0 += 32) {
        bool has_next = (k0 + 32 < K);
        CP_WAIT0();
        __syncthreads();
        if (has_next) issue_tile(k0 + 32, buf ^ 1);

        int bofA = buf * BM * 4;
        int bofB = buf * BN * 4;
        #pragma unroll
        for (int ks = 0; ks < 2; ks++) {
            uint32_t ah[4][4], alo[4][4];
            #pragma unroll
            for (int im = 0; im < 4; im++) {
                int row = m_off + im * 16 + (l & 15);
                int kc = ks * 2 + (l >> 4);
                ldsm_x4(ah[im],  aAh + (bofA + swz(row, kc)) * 16);
                ldsm_x4(alo[im], aAl + (bofA + swz(row, kc)) * 16);
            }
            uint32_t bh2[8][2], bl2[8][2];
            #pragma unroll
            for (int in = 0; in < 8; in++) {
                int row = n_off + in * 8 + (l & 7);
                int kc = ks * 2 + ((l >> 3) & 1);
                ldsm_x2(bh2[in], aBh + (bofB + swz(row, kc)) * 16);
                ldsm_x2(bl2[in], aBl + (bofB + swz(row, kc)) * 16);
            }
            #pragma unroll
            for (int im = 0; im < 4; im++)
                #pragma unroll
                for (int in = 0; in < 8; in++) {
                    mma16816(acc[im][in], ah[im],  bh2[in]);
                    mma16816(acc[im][in], alo[im], bh2[in]);
                    mma16816(acc[im][in], ah[im],  bl2[in]);
                }
        }
        if (has_next) buf ^= 1;
    }

    // ---- epilogue ----
    #pragma unroll
    for (int im = 0; im < 4; im++) {
        int r0 = bm + m_off + im * 16 + (l >> 2);
        #pragma unroll
        for (int in = 0; in < 8; in++) {
            int n = bn + n_off + in * 8 + 2 * (l & 3);
            float b0 = bias ? __ldg(bias + n)     : 0.f;
            float b1 = bias ? __ldg(bias + n + 1) : 0.f;
            float vv[4];
            vv[0] = acc[im][in][0] + b0;
            vv[1] = acc[im][in][1] + b1;
            vv[2] = acc[im][in][2] + b0;
            vv[3] = acc[im][in][3] + b1;
            int rr[4] = {r0, r0, r0 + 8, r0 + 8};
            int cc[4] = {n, n + 1, n, n + 1};
            if (EPI == 0) {
                #pragma unroll
                for (int e = 0; e < 4; e++) {
                    size_t idx = (size_t)rr[e] * N + cc[e];
                    C0[idx] = vv[e];
                    if (C0h) {
                        __nv_bfloat16 h, lo;
                        split1(vv[e], h, lo);
                        C0h[idx] = h;
                        C0l[idx] = lo;
                    }
                }
            } else if (EPI == 1) {
                #pragma unroll
                for (int e = 0; e < 4; e++) {
                    size_t idx = (size_t)rr[e] * N + cc[e];
                    float v = vv[e];
                    float p, dlt;
                    if (v > 15.f) { p = __expf(-v); dlt = v; }
                    else {
                        float ev = __expf(v);
                        p = __fdividef(1.f, 1.f + ev);
                        dlt = __logf(1.f + ev);
                    }
                    C0[idx] = p;
                    C1[idx] = dlt * __ldg(aux + idx);
                }
            } else { // EPI == 3: fused bwd+dbc
                #pragma unroll
                for (int e = 0; e < 4; e++) {
                    int nn = cc[e], m = rr[e];
                    if (nn < 512) {
                        C0[(size_t)m * 512 + nn] = vv[e];
                    } else if (nn < 576) {
                        size_t id = (size_t)m * 64 + (nn - 512);
                        C1[id] = vv[e];
                        __nv_bfloat16 h, lo;
                        split1(vv[e], h, lo);
                        C0h[id] = h;
                        C0l[id] = lo;
                    }
                }
            }
        }
    }
}

// =====================================================================
// v7 64x64 GEMM (proven) — used for the tiny weight-product GEMM
// =====================================================================
template<int BM, int BN, int WMT, int WNT, int NTHR>
__global__ __launch_bounds__(NTHR, 3)
void mma_gemm7(const __nv_bfloat16* __restrict__ Ah,
               const __nv_bfloat16* __restrict__ Al, int lda,
               const __nv_bfloat16* __restrict__ Bh,
               const __nv_bfloat16* __restrict__ Bl, int ldb,
               const float* __restrict__ bias,
               float* __restrict__ C0,
               __nv_bfloat16* __restrict__ C0h,
               __nv_bfloat16* __restrict__ C0l,
               int M, int N, int K)
{
    constexpr int WARPS_N = BN / (WNT * 8);
    constexpr int A_CH = (BM * 4) / NTHR;
    constexpr int B_CH = (BN * 4) / NTHR;

    __shared__ __align__(16) uint4 sAh[2 * BM * 4];
    __shared__ __align__(16) uint4 sAl[2 * BM * 4];
    __shared__ __align__(16) uint4 sBh[2 * BN * 4];
    __shared__ __align__(16) uint4 sBl[2 * BN * 4];

    uint32_t aAh = (uint32_t)__cvta_generic_to_shared(sAh);
    uint32_t aAl = (uint32_t)__cvta_generic_to_shared(sAl);
    uint32_t aBh = (uint32_t)__cvta_generic_to_shared(sBh);
    uint32_t aBl = (uint32_t)__cvta_generic_to_shared(sBl);

    int tid = threadIdx.x;
    int bm = blockIdx.y * BM;
    int bn = blockIdx.x * BN;
    int wid = tid >> 5, l = tid & 31;
    int wn = wid % WARPS_N, wm = wid / WARPS_N;
    int m_off = wm * (WMT * 16);
    int n_off = wn * (WNT * 8);

    float acc[WMT][WNT][4];
    #pragma unroll
    for (int i = 0; i < WMT; i++)
        #pragma unroll
        for (int j = 0; j < WNT; j++)
            #pragma unroll
            for (int c = 0; c < 4; c++) acc[i][j][c] = 0.f;

    auto issue_tile = [&](int k0, int buf) {
        #pragma unroll
        for (int r = 0; r < A_CH; r++) {
            int v = tid + r * NTHR;
            int m = v >> 2, kc = v & 3;
            uint32_t dst = (uint32_t)((buf * BM * 4 + swz(m, kc)) * 16);
            cp16(aAh + dst, Ah + (size_t)(bm + m) * lda + k0 + kc * 8);
            cp16(aAl + dst, Al + (size_t)(bm + m) * lda + k0 + kc * 8);
        }
        #pragma unroll
        for (int r = 0; r < B_CH; r++) {
            int v = tid + r * NTHR;
            int n = v >> 2, kc = v & 3;
            uint32_t dst = (uint32_t)((buf * BN * 4 + swz(n, kc)) * 16);
            cp16(aBh + dst, Bh + (size_t)(bn + n) * ldb + k0 + kc * 8);
            cp16(aBl + dst, Bl + (size_t)(bn + n) * ldb + k0 + kc * 8);
        }
        CP_COMMIT();
    };

    issue_tile(0, 0);

    int buf = 0;
    for (int k0 = 0; k0 < K; k0 += 32) {
        bool has_next = (k0 + 32 < K);
        CP_WAIT0();
        __syncthreads();
        if (has_next) issue_tile(k0 + 32, buf ^ 1);

        int bofA = buf * BM * 4;
        int bofB = buf * BN * 4;
        uint32_t bhf[WNT][4], blf[WNT][4];
        #pragma unroll
        for (int in = 0; in < WNT; in++) {
            int row = n_off + in * 8 + (l & 7);
            int kc = l >> 3;
            ldsm_x4(bhf[in], aBh + (bofB + swz(row, kc)) * 16);
            ldsm_x4(blf[in], aBl + (bofB + swz(row, kc)) * 16);
        }
        #pragma unroll
        for (int ks = 0; ks < 2; ks++) {
            uint32_t ah[WMT][4], alo[WMT][4];
            #pragma unroll
            for (int im = 0; im < WMT; im++) {
                int row = m_off + im * 16 + (l & 15);
                int kc = ks * 2 + (l >> 4);
                ldsm_x4(ah[im],  aAh + (bofA + swz(row, kc)) * 16);
                ldsm_x4(alo[im], aAl + (bofA + swz(row, kc)) * 16);
            }
            #pragma unroll
            for (int im = 0; im < WMT; im++)
                #pragma unroll
                for (int in = 0; in < WNT; in++) {
                    uint32_t bhk[2] = {bhf[in][2*ks], bhf[in][2*ks+1]};
                    uint32_t blk[2] = {blf[in][2*ks], blf[in][2*ks+1]};
                    mma16816(acc[im][in], ah[im], bhk);
                    mma16816(acc[im][in], alo[im], bhk);
                    mma16816(acc[im][in], ah[im], blk);
                }
        }
        if (has_next) buf ^= 1;
    }

    #pragma unroll
    for (int im = 0; im < WMT; im++) {
        int r0 = bm + m_off + im * 16 + (l >> 2);
        #pragma unroll
        for (int in = 0; in < WNT; in++) {
            int n = bn + n_off + in * 8 + 2 * (l & 3);
            float b0 = bias ? __ldg(bias + n)     : 0.f;
            float b1 = bias ? __ldg(bias + n + 1) : 0.f;
            float vv[4];
            vv[0] = acc[im][in][0] + b0;
            vv[1] = acc[im][in][1] + b1;
            vv[2] = acc[im][in][2] + b0;
            vv[3] = acc[im][in][3] + b1;
            size_t i00 = (size_t)r0 * N + n;
            size_t i10 = (size_t)(r0 + 8) * N + n;
            size_t ii[4] = {i00, i00 + 1, i10, i10 + 1};
            #pragma unroll
            for (int e = 0; e < 4; e++) {
                C0[ii[e]] = vv[e];
                if (C0h) {
                    __nv_bfloat16 h, lo;
                    split1(vv[e], h, lo);
                    C0h[ii[e]] = h;
                    C0l[ii[e]] = lo;
                }
            }
        }
    }
}

// =====================================================================
// Scan v3 (unchanged, passing)
// =====================================================================
__device__ __forceinline__ bool a_is_np1(const float* A_log, int d)
{
    bool ok = true;
    #pragma unroll
    for (int n = 0; n < 16; n++) {
        float af = __expf(__ldg(A_log + d * Nc + n));
        float r = rintf(af);
        if (!(fabsf(af - r) < 1e-4f * af) || (int)r != n + 1) ok = false;
    }
    return ok;
}

__global__ __launch_bounds__(256, 2)
void scan_passA2(const float* __restrict__ p,
                 const float* __restrict__ du,
                 const float* __restrict__ dbc,
                 const float* __restrict__ A_log,
                 float* __restrict__ afin,
                 float* __restrict__ hfin)
{
    int bid = blockIdx.x;
    int dg = bid & 1;
    int ch = (bid >> 1) & (NCH - 1);
    int b  = bid / (2 * NCH);
    int d  = dg * 256 + threadIdx.x;

    __shared__ float4 sB[CL][4];
    int srow = b * Sc + ch * CL;
    {
        int i = threadIdx.x;
        if (i < CL * 4) {
            int s = i >> 2, j = i & 3;
            sB[s][j] = *reinterpret_cast<const float4*>(
                dbc + (size_t)(srow + s) * 64 + DTR + j * 4);
        }
    }
    __syncthreads();

    bool np1 = a_is_np1(A_log, d);

    float h[16];
    #pragma unroll
    for (int n = 0; n < 16; n++) h[n] = 0.f;
    float P = 1.f;

    size_t base = (size_t)srow * Dc + d;
    if (np1) {
        #pragma unroll 2
        for (int s = 0; s < CL; ++s) {
            float pv  = p[base];
            float duv = du[base];
            const float* Bv = reinterpret_cast<const float*>(&sB[s][0]);
            float dA[16];
            pow16n(pv, dA);
            P *= pv;
            #pragma unroll
            for (int n = 0; n < 16; n++)
                h[n] = fmaf(dA[n], h[n], duv * Bv[n]);
            base += Dc;
        }
        float Pn[16];
        pow16n(P, Pn);
        size_t t16 = ((size_t)(b * NCH + ch) * Dc + d) * 16;
        float4* ao = reinterpret_cast<float4*>(afin + t16);
        float4* ho = reinterpret_cast<float4*>(hfin + t16);
        #pragma unroll
        for (int q = 0; q < 4; q++) {
            ao[q] = make_float4(Pn[4*q], Pn[4*q+1], Pn[4*q+2], Pn[4*q+3]);
            ho[q] = make_float4(h[4*q],  h[4*q+1],  h[4*q+2],  h[4*q+3]);
        }
    } else {
        float aprod[16];
        #pragma unroll
        for (int n = 0; n < 16; n++) aprod[n] = 1.f;
        for (int s = 0; s < CL; ++s) {
            float pv  = p[base];
            float duv = du[base];
            const float* Bv = reinterpret_cast<const float*>(&sB[s][0]);
            for (int n = 0; n < 16; n++) {
                float af = __expf(__ldg(A_log + d * Nc + n));
                float dA = __powf(pv, af);
                aprod[n] *= dA;
                h[n] = fmaf(dA, h[n], duv * Bv[n]);
            }
            base += Dc;
        }
        size_t t16 = ((size_t)(b * NCH + ch) * Dc + d) * 16;
        for (int n = 0; n < 16; n++) {
            afin[t16 + n] = aprod[n];
            hfin[t16 + n] = h[n];
        }
    }
}

__global__ __launch_bounds__(256)
void scan_mid(const float* __restrict__ afin,
              const float* __restrict__ hfin,
              float* __restrict__ h0)
{
    int t = blockIdx.x * blockDim.x + threadIdx.x;
    int dn = t & (Dc * 16 - 1);
    int b  = t >> 13;
    float run = 0.f;
    #pragma unroll 4
    for (int ch = 0; ch < NCH; ++ch) {
        int tt = ((b * NCH + ch) * Dc * 16) + dn;
        h0[tt] = run;
        run = fmaf(__ldg(afin + tt), run, __ldg(hfin + tt));
    }
}

__global__ __launch_bounds__(256, 2)
void scan_passB2(const float* __restrict__ p,
                 const float* __restrict__ du,
                 const float* __restrict__ dbc,
                 const float* __restrict__ h0,
                 const float* __restrict__ u,
                 const float* __restrict__ z1,
                 const float* __restrict__ x,
                 const float* __restrict__ A_log,
                 const float* __restrict__ D_ssm,
                 float* __restrict__ out)
{
    int bid = blockIdx.x;
    int dg = bid & 1;
    int ch = (bid >> 1) & (NCH - 1);
    int b  = bid / (2 * NCH);
    int d  = dg * 256 + threadIdx.x;

    __shared__ float4 sB[CL][4];
    __shared__ float4 sC[CL][4];
    int srow = b * Sc + ch * CL;
    {
        int i = threadIdx.x;
        int s = i >> 3, j = i & 7;
        float4 v = *reinterpret_cast<const float4*>(
            dbc + (size_t)(srow + s) * 64 + DTR + j * 4);
        if (j < 4) sB[s][j] = v;
        else       sC[s][j - 4] = v;
    }
    __syncthreads();

    bool np1 = a_is_np1(A_log, d);
    float Dd = __ldg(D_ssm + d);

    size_t t16 = ((size_t)(b * NCH + ch) * Dc + d) * 16;
    float h[16];
    {
        const float4* hi = reinterpret_cast<const float4*>(h0 + t16);
        #pragma unroll
        for (int q = 0; q < 4; q++) {
            float4 v = hi[q];
            h[4*q] = v.x; h[4*q+1] = v.y; h[4*q+2] = v.z; h[4*q+3] = v.w;
        }
    }

    size_t base = (size_t)srow * Dc + d;
    if (np1) {
        #pragma unroll 2
        for (int s = 0; s < CL; ++s) {
            float pv  = p[base];
            float duv = du[base];
            const float* Bv = reinterpret_cast<const float*>(&sB[s][0]);
            const float* Cv = reinterpret_cast<const float*>(&sC[s][0]);
            float dA[16];
            pow16n(pv, dA);
            float y0 = 0.f, y1 = 0.f;
            #pragma unroll
            for (int n = 0; n < 16; n++) {
                h[n] = fmaf(dA[n], h[n], duv * Bv[n]);
                if (n & 1) y1 = fmaf(h[n], Cv[n], y1);
                else       y0 = fmaf(h[n], Cv[n], y0);
            }
            float y = y0 + y1;
            float uv = u[base];
            float zv = z1[base];
            float xv = x[base];
            float x2v = y + Dd * uv;
            float sil = __fdividef(zv, 1.f + __expf(-zv));
            out[base] = (zv + x2v) * sil + xv;
            base += Dc;
        }
    } else {
        for (int s = 0; s < CL; ++s) {
            float pv  = p[base];
            float duv = du[base];
            const float* Bv = reinterpret_cast<const float*>(&sB[s][0]);
            const float* Cv = reinterpret_cast<const float*>(&sC[s][0]);
            float y = 0.f;
            for (int n = 0; n < 16; n++) {
                float af = __expf(__ldg(A_log + d * Nc + n));
                float dA = __powf(pv, af);
                h[n] = fmaf(dA, h[n], duv * Bv[n]);
                y = fmaf(h[n], Cv[n], y);
            }
            float uv = u[base];
            float zv = z1[base];
            float xv = x[base];
            float x2v = y + Dd * uv;
            float sil = __fdividef(zv, 1.f + __expf(-zv));
            out[base] = (zv + x2v) * sil + xv;
            base += Dc;
        }
    }
}

// =====================================================================
// launch
// =====================================================================
#define V8_SMEM (4 * 2 * 128 * 4 * 16)   // 65536 bytes

extern "C" void kernel_launch(void* const* d_in, const int* in_sizes, int n_in,
                              void* d_out, int out_size)
{
    const float* x      = (const float*)d_in[0];
    const float* gamma  = (const float*)d_in[1];
    const float* beta   = (const float*)d_in[2];
    const float* W_proj = (const float*)d_in[3];
    const float* b_proj = (const float*)d_in[4];
    // d_in[5] W_fwd, d_in[6] b_fwd: dead code (x1_ssm unused in reference)
    const float* W_bwd  = (const float*)d_in[7];
    const float* b_bwd  = (const float*)d_in[8];
    const float* W_dbc  = (const float*)d_in[9];
    const float* W_dt   = (const float*)d_in[10];
    const float* b_dt   = (const float*)d_in[11];
    const float* A_log  = (const float*)d_in[12];
    const float* D_ssm  = (const float*)d_in[13];
    float* out = (float*)d_out;

    static bool init = false;
    static float *p_z1, *p_bwd, *p_dbc, *p_p, *p_du, *p_afin, *p_hfin, *p_h0,
                 *p_biasf;
    static __nv_bfloat16 *p_xnh, *p_xnl, *p_z1h, *p_z1l,
                         *p_dbch, *p_dbcl, *p_wph, *p_wpl,
                         *p_wfh, *p_wfl, *p_wbrm, *p_wbrml,
                         *p_wdbch, *p_wdbcl, *p_wdth, *p_wdtl;
    if (!init) {
        void* v;
        cudaGetSymbolAddress(&v, g_z1);     p_z1    = (float*)v;
        cudaGetSymbolAddress(&v, g_bwd);    p_bwd   = (float*)v;
        cudaGetSymbolAddress(&v, g_dbc);    p_dbc   = (float*)v;
        cudaGetSymbolAddress(&v, g_p);      p_p     = (float*)v;
        cudaGetSymbolAddress(&v, g_du);     p_du    = (float*)v;
        cudaGetSymbolAddress(&v, g_afin);   p_afin  = (float*)v;
        cudaGetSymbolAddress(&v, g_hfin);   p_hfin  = (float*)v;
        cudaGetSymbolAddress(&v, g_h0);     p_h0    = (float*)v;
        cudaGetSymbolAddress(&v, g_biasf);  p_biasf = (float*)v;
        cudaGetSymbolAddress(&v, g_xnh);    p_xnh   = (__nv_bfloat16*)v;
        cudaGetSymbolAddress(&v, g_xnl);    p_xnl   = (__nv_bfloat16*)v;
        cudaGetSymbolAddress(&v, g_z1h);    p_z1h   = (__nv_bfloat16*)v;
        cudaGetSymbolAddress(&v, g_z1l);    p_z1l   = (__nv_bfloat16*)v;
        cudaGetSymbolAddress(&v, g_dbch);   p_dbch  = (__nv_bfloat16*)v;
        cudaGetSymbolAddress(&v, g_dbcl);   p_dbcl  = (__nv_bfloat16*)v;
        cudaGetSymbolAddress(&v, g_wph);    p_wph   = (__nv_bfloat16*)v;
        cudaGetSymbolAddress(&v, g_wpl);    p_wpl   = (__nv_bfloat16*)v;
        cudaGetSymbolAddress(&v, g_wfuseh); p_wfh   = (__nv_bfloat16*)v;
        cudaGetSymbolAddress(&v, g_wfusel); p_wfl   = (__nv_bfloat16*)v;
        cudaGetSymbolAddress(&v, g_wbrm);   p_wbrm  = (__nv_bfloat16*)v;
        cudaGetSymbolAddress(&v, g_wbrml);  p_wbrml = (__nv_bfloat16*)v;
        cudaGetSymbolAddress(&v, g_wdbch);  p_wdbch = (__nv_bfloat16*)v;
        cudaGetSymbolAddress(&v, g_wdbcl);  p_wdbcl = (__nv_bfloat16*)v;
        cudaGetSymbolAddress(&v, g_wdth);   p_wdth  = (__nv_bfloat16*)v;
        cudaGetSymbolAddress(&v, g_wdtl);   p_wdtl  = (__nv_bfloat16*)v;
        cudaFuncSetAttribute(mma_gemm8<0>,
            cudaFuncAttributeMaxDynamicSharedMemorySize, V8_SMEM);
        cudaFuncSetAttribute(mma_gemm8<1>,
            cudaFuncAttributeMaxDynamicSharedMemorySize, V8_SMEM);
        cudaFuncSetAttribute(mma_gemm8<3>,
            cudaFuncAttributeMaxDynamicSharedMemorySize, V8_SMEM);
        init = true;
    }

    // prep
    ln_kernel<<<BS, 128>>>(x, gamma, beta, p_xnh, p_xnl);
    convert_w<<<(Dc*Dc + 255)/256, 256>>>(W_proj, Dc, Dc, p_wph, p_wpl);
    convert_w<<<(Dc*Dc + 255)/256, 256>>>(W_bwd,  Dc, Dc, p_wfh, p_wfl);     // wfuse rows [0,512)
    convert_rm<<<(Dc*Dc + 255)/256, 256>>>(W_bwd, Dc*Dc, p_wbrm, p_wbrml);
    convert_w<<<(Dc*64 + 255)/256, 256>>>(W_dbc,  Dc, 64, p_wdbch, p_wdbcl);
    convert_w<<<(DTR*Dc + 255)/256, 256>>>(W_dt, DTR, Dc, p_wdth, p_wdtl);

    // Wbd = Wb @ W_dbc in B-format -> wfuse rows [512,576)
    // out[n][k] = sum_j W_dbc[j][n] * Wb[k][j]: A = wdbch [64][512], B = wbrm [512][512]
    {
        dim3 g(Dc/64, 1);
        mma_gemm7<64,64,2,4,128><<<g, 128>>>(
            p_wdbch, p_wdbcl, Dc, p_wbrm, p_wbrml, Dc, nullptr,
            p_afin,  // fp32 scratch (overwritten by scan later)
            p_wfh + 512*Dc, p_wfl + 512*Dc, 64, Dc, Dc);
    }
    biasf_kernel<<<(NF + 127)/128, 128>>>(b_bwd, W_dbc, p_biasf);

    // z1 = xn @ W_proj + b_proj
    {
        dim3 g(Dc/128, BS/128);
        mma_gemm8<0><<<g, 128, V8_SMEM>>>(
            p_xnh, p_xnl, Dc, p_wph, p_wpl, Dc, b_proj,
            p_z1, nullptr, nullptr, p_z1h, p_z1l, BS, Dc, Dc);
    }
    // fused: [bwd | dbc] = z1 @ [Wb | Wbd] + biasf   (N=640, 64 pad cols)
    {
        dim3 g(NF/128, BS/128);   // (5, 64) = 320 CTAs
        mma_gemm8<3><<<g, 128, V8_SMEM>>>(
            p_z1h, p_z1l, Dc, p_wfh, p_wfl, Dc, p_biasf,
            p_bwd, p_dbc, nullptr, p_dbch, p_dbcl, BS, NF, Dc);
    }
    // delta GEMM (K=32) + fused epilogue -> p, du
    {
        dim3 g(Dc/128, BS/128);
        mma_gemm8<1><<<g, 128, V8_SMEM>>>(
            p_dbch, p_dbcl, 64, p_wdth, p_wdtl, DTR, b_dt,
            p_p, p_du, p_bwd, nullptr, nullptr, BS, Dc, DTR);
    }

    // chunk-parallel SSM scan + fused final elementwise
    scan_passA2<<<Bc*NCH*2, 256>>>(p_p, p_du, p_dbc, A_log, p_afin, p_hfin);
    scan_mid<<<(Bc * Dc * Nc) / 256, 256>>>(p_afin, p_hfin, p_h0);
    scan_passB2<<<Bc*NCH*2, 256>>>(p_p, p_du, p_dbc, p_h0,
                                   p_bwd, p_z1, x, A_log, D_ssm, out);
}

// round 15
// speedup vs baseline: 1.0908x; 1.0908x over previous
#include <cuda_runtime.h>
#include <cuda_bf16.h>
#include <math.h>
#include <stdint.h>

#define Bc 4
#define Sc 2048
#define Dc 512
#define Nc 16
#define DTR 32
#define BS (Bc*Sc)
#define BSD (BS*Dc)
#define CL 32
#define NCH (Sc/CL)
#define NSCAN (Bc*NCH*Dc*Nc)

// ---- fp32 scratch ----
__device__ float g_z1[BSD];
__device__ float g_bwd[BSD];
__device__ float g_dbc[BS*64];
__device__ float g_p[BSD];
__device__ float g_du[BSD];
__device__ float g_afin[NSCAN];
__device__ float g_hfin[NSCAN];
__device__ float g_h0[NSCAN];
__device__ int   g_np1flag;

// ---- split-bf16 operand buffers ----
__device__ __nv_bfloat16 g_xnh[BSD],  g_xnl[BSD];
__device__ __nv_bfloat16 g_z1h[BSD],  g_z1l[BSD];
__device__ __nv_bfloat16 g_bwdh[BSD], g_bwdl[BSD];
__device__ __nv_bfloat16 g_dbch[BS*64], g_dbcl[BS*64];
__device__ __nv_bfloat16 g_wph[Dc*Dc], g_wpl[Dc*Dc];
__device__ __nv_bfloat16 g_wbh[Dc*Dc], g_wbl[Dc*Dc];
__device__ __nv_bfloat16 g_wdbch[64*Dc], g_wdbcl[64*Dc];
__device__ __nv_bfloat16 g_wdth[Dc*DTR], g_wdtl[Dc*DTR];

// =====================================================================
// helpers
// =====================================================================
__device__ __forceinline__ void split1(float v, __nv_bfloat16& h, __nv_bfloat16& l)
{
    h = __float2bfloat16(v);
    l = __float2bfloat16(v - __bfloat162float(h));
}

// FMA-pipe exp (no MUFU): |rel err| ~2e-6, clamped to avoid overflow
__device__ __forceinline__ float fexp(float v)
{
    v = fminf(fmaxf(v, -87.f), 87.f);
    float t  = fmaf(v, 1.4426950408889634f, 12582912.f); // +1.5*2^23 round trick
    float fi = t - 12582912.f;
    float x  = fmaf(fi, -0.6931471805599453f, v);        // |x| <= 0.347
    float pl = fmaf(x, 0.008333334f, 0.041666668f);
    pl = fmaf(x, pl, 0.16666667f);
    pl = fmaf(x, pl, 0.5f);
    pl = fmaf(x, pl, 1.f);
    pl = fmaf(x, pl, 1.f);
    int e = (int)fi;
    return pl * __int_as_float((e + 127) << 23);
}

__device__ __forceinline__ void mma16816(float* c, const uint32_t* a, const uint32_t* b)
{
    asm volatile(
        "mma.sync.aligned.m16n8k16.row.col.f32.bf16.bf16.f32 "
        "{%0,%1,%2,%3}, {%4,%5,%6,%7}, {%8,%9}, {%0,%1,%2,%3};\n"
        : "+f"(c[0]), "+f"(c[1]), "+f"(c[2]), "+f"(c[3])
        : "r"(a[0]), "r"(a[1]), "r"(a[2]), "r"(a[3]),
          "r"(b[0]), "r"(b[1]));
}

__device__ __forceinline__ void ldsm_x4(uint32_t* r, uint32_t addr)
{
    asm volatile("ldmatrix.sync.aligned.m8n8.x4.shared.b16 {%0,%1,%2,%3}, [%4];\n"
                 : "=r"(r[0]), "=r"(r[1]), "=r"(r[2]), "=r"(r[3]) : "r"(addr));
}

__device__ __forceinline__ void ldsm_x2(uint32_t* r, uint32_t addr)
{
    asm volatile("ldmatrix.sync.aligned.m8n8.x2.shared.b16 {%0,%1}, [%2];\n"
                 : "=r"(r[0]), "=r"(r[1]) : "r"(addr));
}

__device__ __forceinline__ void cp16(uint32_t dst_smem, const void* src_gmem)
{
    asm volatile("cp.async.ca.shared.global [%0], [%1], 16;\n"
                 :: "r"(dst_smem), "l"(src_gmem) : "memory");
}
#define CP_COMMIT() asm volatile("cp.async.commit_group;\n" ::: "memory")
#define CP_WAIT0()  asm volatile("cp.async.wait_group 0;\n" ::: "memory")

__device__ __forceinline__ int swz(int row, int kc)
{
    return row * 4 + (kc ^ ((row >> 1) & 3));
}

__device__ __forceinline__ void pow16n(float pv, float* dA)
{
    float p1 = pv, p2 = p1*p1, p4 = p2*p2, p8 = p4*p4;
    dA[0]=p1;        dA[1]=p2;        dA[2]=p2*p1;     dA[3]=p4;
    dA[4]=p4*p1;     dA[5]=p4*p2;     dA[6]=p4*dA[2];  dA[7]=p8;
    dA[8]=p8*p1;     dA[9]=p8*p2;     dA[10]=p8*dA[2]; dA[11]=p8*p4;
    dA[12]=p8*dA[4]; dA[13]=p8*dA[5]; dA[14]=p8*dA[6]; dA[15]=p8*p8;
}

// =====================================================================
// np1 structure check: one block, 512 threads (one per d)
// =====================================================================
__global__ void np1_check(const float* __restrict__ A_log, int* __restrict__ flag)
{
    int d = threadIdx.x;
    bool ok = true;
    #pragma unroll
    for (int n = 0; n < 16; n++) {
        float af = __expf(__ldg(A_log + d * Nc + n));
        float r = rintf(af);
        if (!(fabsf(af - r) < 1e-4f * af) || (int)r != n + 1) ok = false;
    }
    int all = __syncthreads_and(ok ? 1 : 0);
    if (d == 0) *flag = all;
}

// =====================================================================
// weight transpose + split
// =====================================================================
__global__ void convert_w(const float* __restrict__ W, int K, int N,
                          __nv_bfloat16* __restrict__ oh,
                          __nv_bfloat16* __restrict__ ol)
{
    int idx = blockIdx.x * blockDim.x + threadIdx.x;
    if (idx >= K * N) return;
    int k = idx / N, n = idx % N;
    __nv_bfloat16 h, l;
    split1(W[idx], h, l);
    oh[n * K + k] = h;
    ol[n * K + k] = l;
}

// =====================================================================
// LayerNorm -> split bf16
// =====================================================================
__global__ void ln_kernel(const float* __restrict__ x,
                          const float* __restrict__ gamma,
                          const float* __restrict__ beta,
                          __nv_bfloat16* __restrict__ xnh,
                          __nv_bfloat16* __restrict__ xnl)
{
    int row = blockIdx.x;
    int tid = threadIdx.x;
    const float4* xr = reinterpret_cast<const float4*>(x + (size_t)row * Dc);
    float4 v = xr[tid];
    float s = v.x + v.y + v.z + v.w;
    float q = v.x*v.x + v.y*v.y + v.z*v.z + v.w*v.w;
    #pragma unroll
    for (int o = 16; o; o >>= 1) {
        s += __shfl_xor_sync(0xffffffffu, s, o);
        q += __shfl_xor_sync(0xffffffffu, q, o);
    }
    __shared__ float ss[4], sq[4];
    if ((tid & 31) == 0) { ss[tid >> 5] = s; sq[tid >> 5] = q; }
    __syncthreads();
    s = ss[0] + ss[1] + ss[2] + ss[3];
    q = sq[0] + sq[1] + sq[2] + sq[3];
    float mean = s * (1.0f / Dc);
    float var  = q * (1.0f / Dc) - mean * mean;
    float rstd = rsqrtf(var + 1e-5f);
    float4 g  = reinterpret_cast<const float4*>(gamma)[tid];
    float4 bt = reinterpret_cast<const float4*>(beta)[tid];
    float ov[4];
    ov[0] = (v.x - mean) * rstd * g.x + bt.x;
    ov[1] = (v.y - mean) * rstd * g.y + bt.y;
    ov[2] = (v.z - mean) * rstd * g.z + bt.z;
    ov[3] = (v.w - mean) * rstd * g.w + bt.w;
    size_t base = (size_t)row * Dc + tid * 4;
    #pragma unroll
    for (int j = 0; j < 4; j++) {
        __nv_bfloat16 h, l;
        split1(ov[j], h, l);
        xnh[base + j] = h;
        xnl[base + j] = l;
    }
}

// =====================================================================
// v8: BM=128 x BN=128 GEMM, 4 warps (64x64 warp tile), dyn smem 64KB
// EPI 0: C0 = v (+ split). EPI 1: dt epilogue (fexp-based)
// =====================================================================
template<int EPI>
__global__ __launch_bounds__(128, 2)
void mma_gemm8(const __nv_bfloat16* __restrict__ Ah,
               const __nv_bfloat16* __restrict__ Al, int lda,
               const __nv_bfloat16* __restrict__ Bh,
               const __nv_bfloat16* __restrict__ Bl, int ldb,
               const float* __restrict__ bias,
               float* __restrict__ C0, float* __restrict__ C1,
               const float* __restrict__ aux,
               __nv_bfloat16* __restrict__ C0h,
               __nv_bfloat16* __restrict__ C0l,
               int M, int N, int K)
{
    constexpr int BM = 128, BN = 128;
    extern __shared__ __align__(16) uint4 dsm[];
    uint4* sAh = dsm;
    uint4* sAl = dsm + 2 * BM * 4;
    uint4* sBh = dsm + 4 * BM * 4;
    uint4* sBl = dsm + 4 * BM * 4 + 2 * BN * 4;

    uint32_t aAh = (uint32_t)__cvta_generic_to_shared(sAh);
    uint32_t aAl = (uint32_t)__cvta_generic_to_shared(sAl);
    uint32_t aBh = (uint32_t)__cvta_generic_to_shared(sBh);
    uint32_t aBl = (uint32_t)__cvta_generic_to_shared(sBl);

    int tid = threadIdx.x;
    int bm = blockIdx.y * BM;
    int bn = blockIdx.x * BN;
    int wid = tid >> 5, l = tid & 31;
    int wn = wid & 1, wm = wid >> 1;
    int m_off = wm * 64;
    int n_off = wn * 64;

    float acc[4][8][4];
    #pragma unroll
    for (int i = 0; i < 4; i++)
        #pragma unroll
        for (int j = 0; j < 8; j++)
            #pragma unroll
            for (int c = 0; c < 4; c++) acc[i][j][c] = 0.f;

    auto issue_tile = [&](int k0, int buf) {
        #pragma unroll
        for (int r = 0; r < 4; r++) {
            int v = tid + r * 128;
            int m = v >> 2, kc = v & 3;
            uint32_t dst = (uint32_t)((buf * BM * 4 + swz(m, kc)) * 16);
            cp16(aAh + dst, Ah + (size_t)(bm + m) * lda + k0 + kc * 8);
            cp16(aAl + dst, Al + (size_t)(bm + m) * lda + k0 + kc * 8);
        }
        #pragma unroll
        for (int r = 0; r < 4; r++) {
            int v = tid + r * 128;
            int n = v >> 2, kc = v & 3;
            uint32_t dst = (uint32_t)((buf * BN * 4 + swz(n, kc)) * 16);
            cp16(aBh + dst, Bh + (size_t)(bn + n) * ldb + k0 + kc * 8);
            cp16(aBl + dst, Bl + (size_t)(bn + n) * ldb + k0 + kc * 8);
        }
        CP_COMMIT();
    };

    issue_tile(0, 0);

    int buf = 0;
    for (int k0 = 0; k0 < K; k0 += 32) {
        bool has_next = (k0 + 32 < K);
        CP_WAIT0();
        __syncthreads();
        if (has_next) issue_tile(k0 + 32, buf ^ 1);

        int bofA = buf * BM * 4;
        int bofB = buf * BN * 4;
        #pragma unroll
        for (int ks = 0; ks < 2; ks++) {
            uint32_t ah[4][4], alo[4][4];
            #pragma unroll
            for (int im = 0; im < 4; im++) {
                int row = m_off + im * 16 + (l & 15);
                int kc = ks * 2 + (l >> 4);
                ldsm_x4(ah[im],  aAh + (bofA + swz(row, kc)) * 16);
                ldsm_x4(alo[im], aAl + (bofA + swz(row, kc)) * 16);
            }
            uint32_t bh2[8][2], bl2[8][2];
            #pragma unroll
            for (int in = 0; in < 8; in++) {
                int row = n_off + in * 8 + (l & 7);
                int kc = ks * 2 + ((l >> 3) & 1);
                ldsm_x2(bh2[in], aBh + (bofB + swz(row, kc)) * 16);
                ldsm_x2(bl2[in], aBl + (bofB + swz(row, kc)) * 16);
            }
            #pragma unroll
            for (int im = 0; im < 4; im++)
                #pragma unroll
                for (int in = 0; in < 8; in++) {
                    mma16816(acc[im][in], ah[im],  bh2[in]);
                    mma16816(acc[im][in], alo[im], bh2[in]);
                    mma16816(acc[im][in], ah[im],  bl2[in]);
                }
        }
        if (has_next) buf ^= 1;
    }

    // ---- epilogue ----
    #pragma unroll
    for (int im = 0; im < 4; im++) {
        int r0 = bm + m_off + im * 16 + (l >> 2);
        #pragma unroll
        for (int in = 0; in < 8; in++) {
            int n = bn + n_off + in * 8 + 2 * (l & 3);
            float b0 = bias ? __ldg(bias + n)     : 0.f;
            float b1 = bias ? __ldg(bias + n + 1) : 0.f;
            float vv[4];
            vv[0] = acc[im][in][0] + b0;
            vv[1] = acc[im][in][1] + b1;
            vv[2] = acc[im][in][2] + b0;
            vv[3] = acc[im][in][3] + b1;
            size_t i00 = (size_t)r0 * N + n;
            size_t i10 = (size_t)(r0 + 8) * N + n;
            size_t ii[4] = {i00, i00 + 1, i10, i10 + 1};
            if (EPI == 0) {
                #pragma unroll
                for (int e = 0; e < 4; e++) {
                    C0[ii[e]] = vv[e];
                    if (C0h) {
                        __nv_bfloat16 h, lo;
                        split1(vv[e], h, lo);
                        C0h[ii[e]] = h;
                        C0l[ii[e]] = lo;
                    }
                }
            } else {
                #pragma unroll
                for (int e = 0; e < 4; e++) {
                    float v = vv[e];
                    float p, dlt;
                    if (v > 15.f) { p = fexp(-v); dlt = v; }
                    else {
                        float ev = fexp(v);            // FMA pipe
                        p = __fdividef(1.f, 1.f + ev); // 1 MUFU
                        dlt = __logf(1.f + ev);        // 1 MUFU
                    }
                    C0[ii[e]] = p;
                    C1[ii[e]] = dlt * __ldg(aux + ii[e]);
                }
            }
        }
    }
}

// =====================================================================
// v7 64x64 GEMM (proven) for the dbc GEMM (N=64)
// =====================================================================
template<int BM, int BN, int WMT, int WNT, int NTHR>
__global__ __launch_bounds__(NTHR, 3)
void mma_gemm7(const __nv_bfloat16* __restrict__ Ah,
               const __nv_bfloat16* __restrict__ Al, int lda,
               const __nv_bfloat16* __restrict__ Bh,
               const __nv_bfloat16* __restrict__ Bl, int ldb,
               const float* __restrict__ bias,
               float* __restrict__ C0,
               __nv_bfloat16* __restrict__ C0h,
               __nv_bfloat16* __restrict__ C0l,
               int M, int N, int K)
{
    constexpr int WARPS_N = BN / (WNT * 8);
    constexpr int A_CH = (BM * 4) / NTHR;
    constexpr int B_CH = (BN * 4) / NTHR;

    __shared__ __align__(16) uint4 sAh[2 * BM * 4];
    __shared__ __align__(16) uint4 sAl[2 * BM * 4];
    __shared__ __align__(16) uint4 sBh[2 * BN * 4];
    __shared__ __align__(16) uint4 sBl[2 * BN * 4];

    uint32_t aAh = (uint32_t)__cvta_generic_to_shared(sAh);
    uint32_t aAl = (uint32_t)__cvta_generic_to_shared(sAl);
    uint32_t aBh = (uint32_t)__cvta_generic_to_shared(sBh);
    uint32_t aBl = (uint32_t)__cvta_generic_to_shared(sBl);

    int tid = threadIdx.x;
    int bm = blockIdx.y * BM;
    int bn = blockIdx.x * BN;
    int wid = tid >> 5, l = tid & 31;
    int wn = wid % WARPS_N, wm = wid / WARPS_N;
    int m_off = wm * (WMT * 16);
    int n_off = wn * (WNT * 8);

    float acc[WMT][WNT][4];
    #pragma unroll
    for (int i = 0; i < WMT; i++)
        #pragma unroll
        for (int j = 0; j < WNT; j++)
            #pragma unroll
            for (int c = 0; c < 4; c++) acc[i][j][c] = 0.f;

    auto issue_tile = [&](int k0, int buf) {
        #pragma unroll
        for (int r = 0; r < A_CH; r++) {
            int v = tid + r * NTHR;
            int m = v >> 2, kc = v & 3;
            uint32_t dst = (uint32_t)((buf * BM * 4 + swz(m, kc)) * 16);
            cp16(aAh + dst, Ah + (size_t)(bm + m) * lda + k0 + kc * 8);
            cp16(aAl + dst, Al + (size_t)(bm + m) * lda + k0 + kc * 8);
        }
        #pragma unroll
        for (int r = 0; r < B_CH; r++) {
            int v = tid + r * NTHR;
            int n = v >> 2, kc = v & 3;
            uint32_t dst = (uint32_t)((buf * BN * 4 + swz(n, kc)) * 16);
            cp16(aBh + dst, Bh + (size_t)(bn + n) * ldb + k0 + kc * 8);
            cp16(aBl + dst, Bl + (size_t)(bn + n) * ldb + k0 + kc * 8);
        }
        CP_COMMIT();
    };

    issue_tile(0, 0);

    int buf = 0;
    for (int k0 = 0; k0 < K; k0 += 32) {
        bool has_next = (k0 + 32 < K);
        CP_WAIT0();
        __syncthreads();
        if (has_next) issue_tile(k0 + 32, buf ^ 1);

        int bofA = buf * BM * 4;
        int bofB = buf * BN * 4;
        uint32_t bhf[WNT][4], blf[WNT][4];
        #pragma unroll
        for (int in = 0; in < WNT; in++) {
            int row = n_off + in * 8 + (l & 7);
            int kc = l >> 3;
            ldsm_x4(bhf[in], aBh + (bofB + swz(row, kc)) * 16);
            ldsm_x4(blf[in], aBl + (bofB + swz(row, kc)) * 16);
        }
        #pragma unroll
        for (int ks = 0; ks < 2; ks++) {
            uint32_t ah[WMT][4], alo[WMT][4];
            #pragma unroll
            for (int im = 0; im < WMT; im++) {
                int row = m_off + im * 16 + (l & 15);
                int kc = ks * 2 + (l >> 4);
                ldsm_x4(ah[im],  aAh + (bofA + swz(row, kc)) * 16);
                ldsm_x4(alo[im], aAl + (bofA + swz(row, kc)) * 16);
            }
            #pragma unroll
            for (int im = 0; im < WMT; im++)
                #pragma unroll
                for (int in = 0; in < WNT; in++) {
                    uint32_t bhk[2] = {bhf[in][2*ks], bhf[in][2*ks+1]};
                    uint32_t blk[2] = {blf[in][2*ks], blf[in][2*ks+1]};
                    mma16816(acc[im][in], ah[im], bhk);
                    mma16816(acc[im][in], alo[im], bhk);
                    mma16816(acc[im][in], ah[im], blk);
                }
        }
        if (has_next) buf ^= 1;
    }

    #pragma unroll
    for (int im = 0; im < WMT; im++) {
        int r0 = bm + m_off + im * 16 + (l >> 2);
        #pragma unroll
        for (int in = 0; in < WNT; in++) {
            int n = bn + n_off + in * 8 + 2 * (l & 3);
            float b0 = bias ? __ldg(bias + n)     : 0.f;
            float b1 = bias ? __ldg(bias + n + 1) : 0.f;
            float vv[4];
            vv[0] = acc[im][in][0] + b0;
            vv[1] = acc[im][in][1] + b1;
            vv[2] = acc[im][in][2] + b0;
            vv[3] = acc[im][in][3] + b1;
            size_t i00 = (size_t)r0 * N + n;
            size_t i10 = (size_t)(r0 + 8) * N + n;
            size_t ii[4] = {i00, i00 + 1, i10, i10 + 1};
            #pragma unroll
            for (int e = 0; e < 4; e++) {
                C0[ii[e]] = vv[e];
                if (C0h) {
                    __nv_bfloat16 h, lo;
                    split1(vv[e], h, lo);
                    C0h[ii[e]] = h;
                    C0l[ii[e]] = lo;
                }
            }
        }
    }
}

// =====================================================================
// Scan v4: np1 via precomputed flag (no per-thread exp setup)
// =====================================================================
__global__ __launch_bounds__(256, 2)
void scan_passA2(const float* __restrict__ p,
                 const float* __restrict__ du,
                 const float* __restrict__ dbc,
                 const float* __restrict__ A_log,
                 const int* __restrict__ np1flag,
                 float* __restrict__ afin,
                 float* __restrict__ hfin)
{
    int bid = blockIdx.x;
    int dg = bid & 1;
    int ch = (bid >> 1) & (NCH - 1);
    int b  = bid / (2 * NCH);
    int d  = dg * 256 + threadIdx.x;

    __shared__ float4 sB[CL][4];
    int srow = b * Sc + ch * CL;
    {
        int i = threadIdx.x;
        if (i < CL * 4) {
            int s = i >> 2, j = i & 3;
            sB[s][j] = *reinterpret_cast<const float4*>(
                dbc + (size_t)(srow + s) * 64 + DTR + j * 4);
        }
    }
    __syncthreads();

    bool np1 = (*np1flag != 0);

    float h[16];
    #pragma unroll
    for (int n = 0; n < 16; n++) h[n] = 0.f;
    float P = 1.f;

    size_t base = (size_t)srow * Dc + d;
    if (np1) {
        #pragma unroll 2
        for (int s = 0; s < CL; ++s) {
            float pv  = p[base];
            float duv = du[base];
            const float* Bv = reinterpret_cast<const float*>(&sB[s][0]);
            float dA[16];
            pow16n(pv, dA);
            P *= pv;
            #pragma unroll
            for (int n = 0; n < 16; n++)
                h[n] = fmaf(dA[n], h[n], duv * Bv[n]);
            base += Dc;
        }
        float Pn[16];
        pow16n(P, Pn);
        size_t t16 = ((size_t)(b * NCH + ch) * Dc + d) * 16;
        float4* ao = reinterpret_cast<float4*>(afin + t16);
        float4* ho = reinterpret_cast<float4*>(hfin + t16);
        #pragma unroll
        for (int q = 0; q < 4; q++) {
            ao[q] = make_float4(Pn[4*q], Pn[4*q+1], Pn[4*q+2], Pn[4*q+3]);
            ho[q] = make_float4(h[4*q],  h[4*q+1],  h[4*q+2],  h[4*q+3]);
        }
    } else {
        float aprod[16];
        #pragma unroll
        for (int n = 0; n < 16; n++) aprod[n] = 1.f;
        for (int s = 0; s < CL; ++s) {
            float pv  = p[base];
            float duv = du[base];
            const float* Bv = reinterpret_cast<const float*>(&sB[s][0]);
            for (int n = 0; n < 16; n++) {
                float af = __expf(__ldg(A_log + d * Nc + n));
                float dA = __powf(pv, af);
                aprod[n] *= dA;
                h[n] = fmaf(dA, h[n], duv * Bv[n]);
            }
            base += Dc;
        }
        size_t t16 = ((size_t)(b * NCH + ch) * Dc + d) * 16;
        for (int n = 0; n < 16; n++) {
            afin[t16 + n] = aprod[n];
            hfin[t16 + n] = h[n];
        }
    }
}

__global__ __launch_bounds__(256)
void scan_mid(const float* __restrict__ afin,
              const float* __restrict__ hfin,
              float* __restrict__ h0)
{
    int t = blockIdx.x * blockDim.x + threadIdx.x;
    int dn = t & (Dc * 16 - 1);
    int b  = t >> 13;
    float run = 0.f;
    #pragma unroll 4
    for (int ch = 0; ch < NCH; ++ch) {
        int tt = ((b * NCH + ch) * Dc * 16) + dn;
        h0[tt] = run;
        run = fmaf(__ldg(afin + tt), run, __ldg(hfin + tt));
    }
}

__global__ __launch_bounds__(256, 2)
void scan_passB2(const float* __restrict__ p,
                 const float* __restrict__ du,
                 const float* __restrict__ dbc,
                 const float* __restrict__ h0,
                 const float* __restrict__ u,
                 const float* __restrict__ z1,
                 const float* __restrict__ x,
                 const float* __restrict__ A_log,
                 const int* __restrict__ np1flag,
                 const float* __restrict__ D_ssm,
                 float* __restrict__ out)
{
    int bid = blockIdx.x;
    int dg = bid & 1;
    int ch = (bid >> 1) & (NCH - 1);
    int b  = bid / (2 * NCH);
    int d  = dg * 256 + threadIdx.x;

    __shared__ float4 sB[CL][4];
    __shared__ float4 sC[CL][4];
    int srow = b * Sc + ch * CL;
    {
        int i = threadIdx.x;
        int s = i >> 3, j = i & 7;
        float4 v = *reinterpret_cast<const float4*>(
            dbc + (size_t)(srow + s) * 64 + DTR + j * 4);
        if (j < 4) sB[s][j] = v;
        else       sC[s][j - 4] = v;
    }
    __syncthreads();

    bool np1 = (*np1flag != 0);
    float Dd = __ldg(D_ssm + d);

    size_t t16 = ((size_t)(b * NCH + ch) * Dc + d) * 16;
    float h[16];
    {
        const float4* hi = reinterpret_cast<const float4*>(h0 + t16);
        #pragma unroll
        for (int q = 0; q < 4; q++) {
            float4 v = hi[q];
            h[4*q] = v.x; h[4*q+1] = v.y; h[4*q+2] = v.z; h[4*q+3] = v.w;
        }
    }

    size_t base = (size_t)srow * Dc + d;
    if (np1) {
        #pragma unroll 2
        for (int s = 0; s < CL; ++s) {
            float pv  = p[base];
            float duv = du[base];
            const float* Bv = reinterpret_cast<const float*>(&sB[s][0]);
            const float* Cv = reinterpret_cast<const float*>(&sC[s][0]);
            float dA[16];
            pow16n(pv, dA);
            float y0 = 0.f, y1 = 0.f;
            #pragma unroll
            for (int n = 0; n < 16; n++) {
                h[n] = fmaf(dA[n], h[n], duv * Bv[n]);
                if (n & 1) y1 = fmaf(h[n], Cv[n], y1);
                else       y0 = fmaf(h[n], Cv[n], y0);
            }
            float y = y0 + y1;
            float uv = u[base];
            float zv = z1[base];
            float xv = x[base];
            float x2v = y + Dd * uv;
            float sil = __fdividef(zv, 1.f + fexp(-zv));
            out[base] = (zv + x2v) * sil + xv;
            base += Dc;
        }
    } else {
        for (int s = 0; s < CL; ++s) {
            float pv  = p[base];
            float duv = du[base];
            const float* Bv = reinterpret_cast<const float*>(&sB[s][0]);
            const float* Cv = reinterpret_cast<const float*>(&sC[s][0]);
            float y = 0.f;
            for (int n = 0; n < 16; n++) {
                float af = __expf(__ldg(A_log + d * Nc + n));
                float dA = __powf(pv, af);
                h[n] = fmaf(dA, h[n], duv * Bv[n]);
                y = fmaf(h[n], Cv[n], y);
            }
            float uv = u[base];
            float zv = z1[base];
            float xv = x[base];
            float x2v = y + Dd * uv;
            float sil = __fdividef(zv, 1.f + fexp(-zv));
            out[base] = (zv + x2v) * sil + xv;
            base += Dc;
        }
    }
}

// =====================================================================
// launch  (R13 structure + np1 flag + fexp epilogues)
// =====================================================================
#define V8_SMEM (4 * 2 * 128 * 4 * 16)   // 65536 bytes

extern "C" void kernel_launch(void* const* d_in, const int* in_sizes, int n_in,
                              void* d_out, int out_size)
{
    const float* x      = (const float*)d_in[0];
    const float* gamma  = (const float*)d_in[1];
    const float* beta   = (const float*)d_in[2];
    const float* W_proj = (const float*)d_in[3];
    const float* b_proj = (const float*)d_in[4];
    // d_in[5] W_fwd, d_in[6] b_fwd: dead code (x1_ssm unused in reference)
    const float* W_bwd  = (const float*)d_in[7];
    const float* b_bwd  = (const float*)d_in[8];
    const float* W_dbc  = (const float*)d_in[9];
    const float* W_dt   = (const float*)d_in[10];
    const float* b_dt   = (const float*)d_in[11];
    const float* A_log  = (const float*)d_in[12];
    const float* D_ssm  = (const float*)d_in[13];
    float* out = (float*)d_out;

    static bool init = false;
    static float *p_z1, *p_bwd, *p_dbc, *p_p, *p_du, *p_afin, *p_hfin, *p_h0;
    static int* p_flag;
    static __nv_bfloat16 *p_xnh, *p_xnl, *p_z1h, *p_z1l, *p_bwdh, *p_bwdl,
                         *p_dbch, *p_dbcl, *p_wph, *p_wpl, *p_wbh, *p_wbl,
                         *p_wdbch, *p_wdbcl, *p_wdth, *p_wdtl;
    if (!init) {
        void* v;
        cudaGetSymbolAddress(&v, g_z1);      p_z1    = (float*)v;
        cudaGetSymbolAddress(&v, g_bwd);     p_bwd   = (float*)v;
        cudaGetSymbolAddress(&v, g_dbc);     p_dbc   = (float*)v;
        cudaGetSymbolAddress(&v, g_p);       p_p     = (float*)v;
        cudaGetSymbolAddress(&v, g_du);      p_du    = (float*)v;
        cudaGetSymbolAddress(&v, g_afin);    p_afin  = (float*)v;
        cudaGetSymbolAddress(&v, g_hfin);    p_hfin  = (float*)v;
        cudaGetSymbolAddress(&v, g_h0);      p_h0    = (float*)v;
        cudaGetSymbolAddress(&v, g_np1flag); p_flag  = (int*)v;
        cudaGetSymbolAddress(&v, g_xnh);     p_xnh   = (__nv_bfloat16*)v;
        cudaGetSymbolAddress(&v, g_xnl);     p_xnl   = (__nv_bfloat16*)v;
        cudaGetSymbolAddress(&v, g_z1h);     p_z1h   = (__nv_bfloat16*)v;
        cudaGetSymbolAddress(&v, g_z1l);     p_z1l   = (__nv_bfloat16*)v;
        cudaGetSymbolAddress(&v, g_bwdh);    p_bwdh  = (__nv_bfloat16*)v;
        cudaGetSymbolAddress(&v, g_bwdl);    p_bwdl  = (__nv_bfloat16*)v;
        cudaGetSymbolAddress(&v, g_dbch);    p_dbch  = (__nv_bfloat16*)v;
        cudaGetSymbolAddress(&v, g_dbcl);    p_dbcl  = (__nv_bfloat16*)v;
        cudaGetSymbolAddress(&v, g_wph);     p_wph   = (__nv_bfloat16*)v;
        cudaGetSymbolAddress(&v, g_wpl);     p_wpl   = (__nv_bfloat16*)v;
        cudaGetSymbolAddress(&v, g_wbh);     p_wbh   = (__nv_bfloat16*)v;
        cudaGetSymbolAddress(&v, g_wbl);     p_wbl   = (__nv_bfloat16*)v;
        cudaGetSymbolAddress(&v, g_wdbch);   p_wdbch = (__nv_bfloat16*)v;
        cudaGetSymbolAddress(&v, g_wdbcl);   p_wdbcl = (__nv_bfloat16*)v;
        cudaGetSymbolAddress(&v, g_wdth);    p_wdth  = (__nv_bfloat16*)v;
        cudaGetSymbolAddress(&v, g_wdtl);    p_wdtl  = (__nv_bfloat16*)v;
        cudaFuncSetAttribute(mma_gemm8<0>,
            cudaFuncAttributeMaxDynamicSharedMemorySize, V8_SMEM);
        cudaFuncSetAttribute(mma_gemm8<1>,
            cudaFuncAttributeMaxDynamicSharedMemorySize, V8_SMEM);
        init = true;
    }

    ln_kernel<<<BS, 128>>>(x, gamma, beta, p_xnh, p_xnl);
    convert_w<<<(Dc*Dc + 255)/256, 256>>>(W_proj, Dc, Dc, p_wph, p_wpl);
    convert_w<<<(Dc*Dc + 255)/256, 256>>>(W_bwd,  Dc, Dc, p_wbh, p_wbl);
    np1_check<<<1, Dc>>>(A_log, p_flag);

    // z1 = xn @ W_proj + b_proj
    {
        dim3 g(Dc/128, BS/128);
        mma_gemm8<0><<<g, 128, V8_SMEM>>>(
            p_xnh, p_xnl, Dc, p_wph, p_wpl, Dc, b_proj,
            p_z1, nullptr, nullptr, p_z1h, p_z1l, BS, Dc, Dc);
    }
    // bwd = z1 @ W_bwd + b_bwd
    {
        dim3 g(Dc/128, BS/128);
        mma_gemm8<0><<<g, 128, V8_SMEM>>>(
            p_z1h, p_z1l, Dc, p_wbh, p_wbl, Dc, b_bwd,
            p_bwd, nullptr, nullptr, p_bwdh, p_bwdl, BS, Dc, Dc);
    }
    convert_w<<<(Dc*64 + 255)/256, 256>>>(W_dbc,  Dc, 64, p_wdbch, p_wdbcl);
    convert_w<<<(DTR*Dc + 255)/256, 256>>>(W_dt, DTR, Dc, p_wdth, p_wdtl);

    // dbc = bwd @ W_dbc  (N=64, v7 path)
    {
        dim3 g(1, BS/64);
        mma_gemm7<64,64,2,4,128><<<g, 128>>>(
            p_bwdh, p_bwdl, Dc, p_wdbch, p_wdbcl, Dc, nullptr,
            p_dbc, p_dbch, p_dbcl, BS, 64, Dc);
    }
    // delta GEMM (K=32) + fused fexp epilogue -> p, du
    {
        dim3 g(Dc/128, BS/128);
        mma_gemm8<1><<<g, 128, V8_SMEM>>>(
            p_dbch, p_dbcl, 64, p_wdth, p_wdtl, DTR, b_dt,
            p_p, p_du, p_bwd, nullptr, nullptr, BS, Dc, DTR);
    }

    // chunk-parallel SSM scan + fused final elementwise
    scan_passA2<<<Bc*NCH*2, 256>>>(p_p, p_du, p_dbc, A_log, p_flag,
                                   p_afin, p_hfin);
    scan_mid<<<(Bc * Dc * Nc) / 256, 256>>>(p_afin, p_hfin, p_h0);
    scan_passB2<<<Bc*NCH*2, 256>>>(p_p, p_du, p_dbc, p_h0,
                                   p_bwd, p_z1, x, A_log, p_flag, D_ssm, out);
}